// round 14
// baseline (speedup 1.0000x reference)
#include <cuda_runtime.h>
#include <math.h>

#define NN 50000
#define EE 800000
#define ET (EE + NN)
#define FIN 256
#define HH 64
#define CC 40
#define NEG_SLOPE 0.2f
#define NB ((NN + 255) / 256)

typedef unsigned long long u64;

// ---------------- scratch (__device__ globals; no allocation) ----------------
static __device__ int g_is64;
static __device__ int g_src[ET];
static __device__ int g_dst[ET];
static __device__ int g_cnt[NN];
static __device__ int g_roff[NN + 1];
static __device__ int g_cursor[NN];
static __device__ int g_csrc[ET];
static __device__ int g_bsum[NB];
static __device__ int g_bpre[NB];

static __device__ float g_xl1[NN * HH];
static __device__ float g_xr1[NN * HH];
static __device__ float g_ln1[NN * HH];
static __device__ float g_h[NN * HH];

static __device__ float g_xl2[NN * CC];
static __device__ float g_xr2[NN * CC];
static __device__ float g_ln2[NN * CC];

__device__ __forceinline__ float lrelu(float v) { return fmaxf(v, NEG_SLOPE * v); }

__device__ __forceinline__ unsigned f2tf32(float v) {
    unsigned r;
    asm("cvt.rna.tf32.f32 %0, %1;" : "=r"(r) : "f"(v));
    return r;
}

__device__ __forceinline__ void mma_tf32(float c[4], unsigned a0, unsigned a1,
                                         unsigned a2, unsigned a3,
                                         unsigned b0, unsigned b1) {
    asm("mma.sync.aligned.m16n8k8.row.col.f32.tf32.tf32.f32 "
        "{%0,%1,%2,%3}, {%4,%5,%6,%7}, {%8,%9}, {%0,%1,%2,%3};"
        : "+f"(c[0]), "+f"(c[1]), "+f"(c[2]), "+f"(c[3])
        : "r"(a0), "r"(a1), "r"(a2), "r"(a3), "r"(b0), "r"(b1));
}

// ---------------- init: zero counts + edge dtype detect (fused) ----------------
__global__ void init_kernel(const void* edge) {
    int i = blockIdx.x * blockDim.x + threadIdx.x;
    if (i < NN) g_cnt[i] = 0;
    if (blockIdx.x == 0 && threadIdx.x < 32) {
        const int* p = (const int*)edge;
        int ok = 1;
        for (int j = threadIdx.x * 2 + 1; j < 4096; j += 64)
            if (p[j] != 0) ok = 0;
        unsigned b = __ballot_sync(0xffffffffu, ok);
        if (threadIdx.x == 0) g_is64 = (b == 0xffffffffu) ? 1 : 0;
    }
}

// convert edge list (+self loops), histogram dst, emit edge_index passthrough
__global__ void convert_count_kernel(const void* edge, float* __restrict__ out, int do_pass) {
    int t = blockIdx.x * blockDim.x + threadIdx.x;
    if (t >= ET) return;
    int s, d;
    if (t >= EE) {
        s = t - EE; d = t - EE;
    } else if (g_is64) {
        const long long* p = (const long long*)edge;
        s = (int)p[t]; d = (int)p[EE + t];
    } else {
        const int* p = (const int*)edge;
        s = p[t]; d = p[EE + t];
    }
    g_src[t] = s;
    g_dst[t] = d;
    atomicAdd(&g_cnt[d], 1);
    if (do_pass && t < EE) {
        out[NN * CC + t] = (float)s;
        out[NN * CC + EE + t] = (float)d;
    }
}

// ---------------- 3-stage parallel scan over g_cnt ----------------
__global__ void bsum_kernel() {
    __shared__ int ws[8];
    int i = blockIdx.x * 256 + threadIdx.x;
    int lane = threadIdx.x & 31, w = threadIdx.x >> 5;
    int v = (i < NN) ? g_cnt[i] : 0;
#pragma unroll
    for (int o = 16; o > 0; o >>= 1) v += __shfl_xor_sync(0xffffffffu, v, o);
    if (lane == 0) ws[w] = v;
    __syncthreads();
    if (threadIdx.x == 0) {
        int s = 0;
#pragma unroll
        for (int k = 0; k < 8; k++) s += ws[k];
        g_bsum[blockIdx.x] = s;
    }
}

__global__ void bscan_kernel() {  // 1 block, 256 threads; NB <= 256
    __shared__ int ws[8];
    int t = threadIdx.x;
    int lane = t & 31, w = t >> 5;
    int v = (t < NB) ? g_bsum[t] : 0;
    int x = v;
#pragma unroll
    for (int dlt = 1; dlt < 32; dlt <<= 1) {
        int y = __shfl_up_sync(0xffffffffu, x, dlt);
        if (lane >= dlt) x += y;
    }
    if (lane == 31) ws[w] = x;
    __syncthreads();
    if (w == 0 && lane < 8) {
        int s = ws[lane];
#pragma unroll
        for (int dlt = 1; dlt < 8; dlt <<= 1) {
            int y = __shfl_up_sync(0xffu, s, dlt);
            if (lane >= dlt) s += y;
        }
        ws[lane] = s;
    }
    __syncthreads();
    int prefix = (w > 0) ? ws[w - 1] : 0;
    if (t < NB) g_bpre[t] = prefix + x - v;
}

__global__ void offs_kernel() {
    __shared__ int ws[8];
    int i = blockIdx.x * 256 + threadIdx.x;
    int lane = threadIdx.x & 31, w = threadIdx.x >> 5;
    int v = (i < NN) ? g_cnt[i] : 0;
    int x = v;
#pragma unroll
    for (int dlt = 1; dlt < 32; dlt <<= 1) {
        int y = __shfl_up_sync(0xffffffffu, x, dlt);
        if (lane >= dlt) x += y;
    }
    if (lane == 31) ws[w] = x;
    __syncthreads();
    if (w == 0 && lane < 8) {
        int s = ws[lane];
#pragma unroll
        for (int dlt = 1; dlt < 8; dlt <<= 1) {
            int y = __shfl_up_sync(0xffu, s, dlt);
            if (lane >= dlt) s += y;
        }
        ws[lane] = s;
    }
    __syncthreads();
    int prefix = (w > 0) ? ws[w - 1] : 0;
    int excl = g_bpre[blockIdx.x] + prefix + x - v;
    if (i < NN) {
        g_cursor[i] = excl;
        g_roff[i + 1] = excl + v;
    }
    if (i == 0) g_roff[0] = 0;
}

__global__ void scatter_kernel() {
    int t = blockIdx.x * blockDim.x + threadIdx.x;
    if (t >= ET) return;
    int d = g_dst[t];
    int pos = atomicAdd(&g_cursor[d], 1);
    g_csrc[pos] = g_src[t];
}

// ---------------- layer1 node GEMMs: tf32 MMA (R9 config, proven 61.7us) ----------
__global__ void __launch_bounds__(256) gemm1_kernel(
    const float* __restrict__ x,
    const float* __restrict__ W1l, const float* __restrict__ b1l,
    const float* __restrict__ W1r, const float* __restrict__ b1r,
    const float* __restrict__ Wn, const float* __restrict__ bn) {
    __shared__ unsigned As[128][20];
    __shared__ unsigned Bs[16][72];
    const int tid = threadIdx.x;
    const int warp = tid >> 5, lane = tid & 31;
    const int gid = lane >> 2, tig = lane & 3;
    const int mat = blockIdx.y;
    const float* W    = (mat == 0) ? W1l : ((mat == 1) ? W1r : Wn);
    const float* bias = (mat == 0) ? b1l : ((mat == 1) ? b1r : bn);
    float* outp       = (mat == 0) ? g_xl1 : ((mat == 1) ? g_xr1 : g_ln1);
    const int m0 = blockIdx.x * 128;
    const int r0 = m0 + warp * 16 + gid, r1 = r0 + 8;

    float acc[8][4];
#pragma unroll
    for (int i = 0; i < 8; i++) {
        acc[i][0] = 0.f; acc[i][1] = 0.f; acc[i][2] = 0.f; acc[i][3] = 0.f;
    }

    for (int ks = 0; ks < FIN; ks += 16) {
        __syncthreads();
        {
            int kk = tid >> 4;
            int c = (tid & 15) * 4;
            float4 wv = *(const float4*)&W[(ks + kk) * HH + c];
            Bs[kk][c + 0] = f2tf32(wv.x);
            Bs[kk][c + 1] = f2tf32(wv.y);
            Bs[kk][c + 2] = f2tf32(wv.z);
            Bs[kk][c + 3] = f2tf32(wv.w);
        }
#pragma unroll
        for (int j = 0; j < 2; j++) {
            int f = tid + j * 256;
            int r = f >> 2;
            int c4 = (f & 3) * 4;
            int rr = m0 + r;
            float4 v = make_float4(0.f, 0.f, 0.f, 0.f);
            if (rr < NN) v = *(const float4*)&x[rr * FIN + ks + c4];
            As[r][c4 + 0] = f2tf32(v.x);
            As[r][c4 + 1] = f2tf32(v.y);
            As[r][c4 + 2] = f2tf32(v.z);
            As[r][c4 + 3] = f2tf32(v.w);
        }
        __syncthreads();

#pragma unroll
        for (int half = 0; half < 2; half++) {
            int kb = half * 8 + tig;
            int ra = warp * 16 + gid, rb = ra + 8;
            unsigned a0 = As[ra][kb];
            unsigned a1 = As[rb][kb];
            unsigned a2 = As[ra][kb + 4];
            unsigned a3 = As[rb][kb + 4];
#pragma unroll
            for (int nc = 0; nc < 8; nc++) {
                unsigned b0 = Bs[kb][nc * 8 + gid];
                unsigned b1 = Bs[kb + 4][nc * 8 + gid];
                mma_tf32(acc[nc], a0, a1, a2, a3, b0, b1);
            }
        }
    }

#pragma unroll
    for (int nc = 0; nc < 8; nc++) {
        int n = nc * 8 + tig * 2;
        float b0v = __ldg(&bias[n]);
        float b1v = __ldg(&bias[n + 1]);
        if (r0 < NN)
            *(float2*)&outp[r0 * HH + n] = make_float2(acc[nc][0] + b0v, acc[nc][1] + b1v);
        if (r1 < NN)
            *(float2*)&outp[r1 * HH + n] = make_float2(acc[nc][2] + b0v, acc[nc][3] + b1v);
    }
}

// ---------------- layer1 attention: warp/node, 4 groups, PAIRWISE + prefetch ----
__global__ void attn1_kernel(const float* __restrict__ att,
                             const float* __restrict__ bias1) {
    int w = (blockIdx.x * blockDim.x + threadIdx.x) >> 5;
    int lane = threadIdx.x & 31;
    if (w >= NN) return;
    int grp = lane >> 3, sub = lane & 7;
    const unsigned gmask = 0xFFu << (grp * 8);

    const float4* xl4 = (const float4*)g_xl1;
    float4 xrA = ((const float4*)g_xr1)[w * 16 + sub * 2];
    float4 xrB = ((const float4*)g_xr1)[w * 16 + sub * 2 + 1];
    float4 atA = ((const float4*)att)[sub * 2];
    float4 atB = ((const float4*)att)[sub * 2 + 1];

    int beg = g_roff[w], end = g_roff[w + 1];

    float mx = -1e30f, den = 0.f;
    float4 aA = make_float4(0.f, 0.f, 0.f, 0.f);
    float4 aB = make_float4(0.f, 0.f, 0.f, 0.f);

    int e = beg + grp;
    // current pair (e, e+4)
    float4 vA0 = make_float4(0.f, 0.f, 0.f, 0.f), vB0 = vA0;
    float4 vA1 = vA0, vB1 = vA0;
    if (e < end) {
        int s = g_csrc[e];
        vA0 = xl4[s * 16 + sub * 2];
        vB0 = xl4[s * 16 + sub * 2 + 1];
    }
    if (e + 4 < end) {
        int s = g_csrc[e + 4];
        vA1 = xl4[s * 16 + sub * 2];
        vB1 = xl4[s * 16 + sub * 2 + 1];
    }
    while (e < end) {
        int en = e + 8;
        // prefetch next pair
        float4 nA0 = make_float4(0.f, 0.f, 0.f, 0.f), nB0 = nA0;
        float4 nA1 = nA0, nB1 = nA0;
        if (en < end) {
            int s = g_csrc[en];
            nA0 = xl4[s * 16 + sub * 2];
            nB0 = xl4[s * 16 + sub * 2 + 1];
        }
        if (en + 4 < end) {
            int s = g_csrc[en + 4];
            nA1 = xl4[s * 16 + sub * 2];
            nB1 = xl4[s * 16 + sub * 2 + 1];
        }
        // two independent logit chains
        float pA = lrelu(vA0.x + xrA.x) * atA.x + lrelu(vA0.y + xrA.y) * atA.y
                 + lrelu(vA0.z + xrA.z) * atA.z + lrelu(vA0.w + xrA.w) * atA.w
                 + lrelu(vB0.x + xrB.x) * atB.x + lrelu(vB0.y + xrB.y) * atB.y
                 + lrelu(vB0.z + xrB.z) * atB.z + lrelu(vB0.w + xrB.w) * atB.w;
        float pB = lrelu(vA1.x + xrA.x) * atA.x + lrelu(vA1.y + xrA.y) * atA.y
                 + lrelu(vA1.z + xrA.z) * atA.z + lrelu(vA1.w + xrA.w) * atA.w
                 + lrelu(vB1.x + xrB.x) * atB.x + lrelu(vB1.y + xrB.y) * atB.y
                 + lrelu(vB1.z + xrB.z) * atB.z + lrelu(vB1.w + xrB.w) * atB.w;
        pA += __shfl_xor_sync(gmask, pA, 1);
        pB += __shfl_xor_sync(gmask, pB, 1);
        pA += __shfl_xor_sync(gmask, pA, 2);
        pB += __shfl_xor_sync(gmask, pB, 2);
        pA += __shfl_xor_sync(gmask, pA, 4);
        pB += __shfl_xor_sync(gmask, pB, 4);
        if (e + 4 >= end) pB = -1e30f;  // uniform per group
        // single merged rescale for the pair
        float nmx = fmaxf(mx, fmaxf(pA, pB));
        float sc = __expf(mx - nmx);
        float wA = __expf(pA - nmx);
        float wB = __expf(pB - nmx);
        den = den * sc + wA + wB;
        aA.x = fmaf(aA.x, sc, fmaf(wA, vA0.x, wB * vA1.x));
        aA.y = fmaf(aA.y, sc, fmaf(wA, vA0.y, wB * vA1.y));
        aA.z = fmaf(aA.z, sc, fmaf(wA, vA0.z, wB * vA1.z));
        aA.w = fmaf(aA.w, sc, fmaf(wA, vA0.w, wB * vA1.w));
        aB.x = fmaf(aB.x, sc, fmaf(wA, vB0.x, wB * vB1.x));
        aB.y = fmaf(aB.y, sc, fmaf(wA, vB0.y, wB * vB1.y));
        aB.z = fmaf(aB.z, sc, fmaf(wA, vB0.z, wB * vB1.z));
        aB.w = fmaf(aB.w, sc, fmaf(wA, vB0.w, wB * vB1.w));
        mx = nmx;
        e = en;
        vA0 = nA0; vB0 = nB0; vA1 = nA1; vB1 = nB1;
    }

    // merge the 4 group states (warp reconverged; full mask safe)
#pragma unroll
    for (int msk = 8; msk <= 16; msk <<= 1) {
        float omx = __shfl_xor_sync(0xffffffffu, mx, msk);
        float nmx = fmaxf(mx, omx);
        float sc = __expf(mx - nmx);
        den *= sc;
        aA.x *= sc; aA.y *= sc; aA.z *= sc; aA.w *= sc;
        aB.x *= sc; aB.y *= sc; aB.z *= sc; aB.w *= sc;
        den += __shfl_xor_sync(0xffffffffu, den, msk);
        aA.x += __shfl_xor_sync(0xffffffffu, aA.x, msk);
        aA.y += __shfl_xor_sync(0xffffffffu, aA.y, msk);
        aA.z += __shfl_xor_sync(0xffffffffu, aA.z, msk);
        aA.w += __shfl_xor_sync(0xffffffffu, aA.w, msk);
        aB.x += __shfl_xor_sync(0xffffffffu, aB.x, msk);
        aB.y += __shfl_xor_sync(0xffffffffu, aB.y, msk);
        aB.z += __shfl_xor_sync(0xffffffffu, aB.z, msk);
        aB.w += __shfl_xor_sync(0xffffffffu, aB.w, msk);
        mx = nmx;
    }

    if (grp == 0) {
        float inv = 1.f / den;
        float4 lnA = ((const float4*)g_ln1)[w * 16 + sub * 2];
        float4 lnB = ((const float4*)g_ln1)[w * 16 + sub * 2 + 1];
        float4 bA = ((const float4*)bias1)[sub * 2];
        float4 bB = ((const float4*)bias1)[sub * 2 + 1];
        float4 hA, hB;
        hA.x = fmaxf(fmaf(aA.x, inv, bA.x + lnA.x), 0.f);
        hA.y = fmaxf(fmaf(aA.y, inv, bA.y + lnA.y), 0.f);
        hA.z = fmaxf(fmaf(aA.z, inv, bA.z + lnA.z), 0.f);
        hA.w = fmaxf(fmaf(aA.w, inv, bA.w + lnA.w), 0.f);
        hB.x = fmaxf(fmaf(aB.x, inv, bB.x + lnB.x), 0.f);
        hB.y = fmaxf(fmaf(aB.y, inv, bB.y + lnB.y), 0.f);
        hB.z = fmaxf(fmaf(aB.z, inv, bB.z + lnB.z), 0.f);
        hB.w = fmaxf(fmaf(aB.w, inv, bB.w + lnB.w), 0.f);
        ((float4*)g_h)[w * 16 + sub * 2] = hA;
        ((float4*)g_h)[w * 16 + sub * 2 + 1] = hB;
    }
}

// ---------------- layer2 node GEMMs: tf32 MMA, R9 shape, CC=40 = 5 n8 blocks ----
__global__ void __launch_bounds__(256) gemm2_kernel(
    const float* __restrict__ Wl, const float* __restrict__ bl,
    const float* __restrict__ Wr, const float* __restrict__ br,
    const float* __restrict__ Wn, const float* __restrict__ bn) {
    __shared__ unsigned As[128][20];
    __shared__ unsigned Bs[16][40];
    const int tid = threadIdx.x;
    const int warp = tid >> 5, lane = tid & 31;
    const int gid = lane >> 2, tig = lane & 3;
    const int mat = blockIdx.y;
    const float* W    = (mat == 0) ? Wl : ((mat == 1) ? Wr : Wn);
    const float* bias = (mat == 0) ? bl : ((mat == 1) ? br : bn);
    float* outp       = (mat == 0) ? g_xl2 : ((mat == 1) ? g_xr2 : g_ln2);
    const int m0 = blockIdx.x * 128;
    const int r0 = m0 + warp * 16 + gid, r1 = r0 + 8;

    float acc[5][4];
#pragma unroll
    for (int i = 0; i < 5; i++) {
        acc[i][0] = 0.f; acc[i][1] = 0.f; acc[i][2] = 0.f; acc[i][3] = 0.f;
    }

    for (int ks = 0; ks < HH; ks += 16) {
        __syncthreads();
#pragma unroll
        for (int j = 0; j < 3; j++) {
            int f = tid + j * 256;
            if (f < 640) {
                int kk = f / 40;
                int c = f - kk * 40;
                Bs[kk][c] = f2tf32(__ldg(&W[(ks + kk) * CC + c]));
            }
        }
#pragma unroll
        for (int j = 0; j < 2; j++) {
            int f = tid + j * 256;
            int r = f >> 2;
            int c4 = (f & 3) * 4;
            int rr = m0 + r;
            float4 v = make_float4(0.f, 0.f, 0.f, 0.f);
            if (rr < NN) v = *(const float4*)&g_h[rr * HH + ks + c4];
            As[r][c4 + 0] = f2tf32(v.x);
            As[r][c4 + 1] = f2tf32(v.y);
            As[r][c4 + 2] = f2tf32(v.z);
            As[r][c4 + 3] = f2tf32(v.w);
        }
        __syncthreads();

#pragma unroll
        for (int half = 0; half < 2; half++) {
            int kb = half * 8 + tig;
            int ra = warp * 16 + gid, rb = ra + 8;
            unsigned a0 = As[ra][kb];
            unsigned a1 = As[rb][kb];
            unsigned a2 = As[ra][kb + 4];
            unsigned a3 = As[rb][kb + 4];
#pragma unroll
            for (int nc = 0; nc < 5; nc++) {
                unsigned b0 = Bs[kb][nc * 8 + gid];
                unsigned b1 = Bs[kb + 4][nc * 8 + gid];
                mma_tf32(acc[nc], a0, a1, a2, a3, b0, b1);
            }
        }
    }

#pragma unroll
    for (int nc = 0; nc < 5; nc++) {
        int n = nc * 8 + tig * 2;
        float b0v = __ldg(&bias[n]);
        float b1v = __ldg(&bias[n + 1]);
        if (r0 < NN)
            *(float2*)&outp[r0 * CC + n] = make_float2(acc[nc][0] + b0v, acc[nc][1] + b1v);
        if (r1 < NN)
            *(float2*)&outp[r1 * CC + n] = make_float2(acc[nc][2] + b0v, acc[nc][3] + b1v);
    }
}

// ---------------- layer2 attention + log_softmax: 2 groups, PAIRWISE + prefetch ----
__global__ void attn2_kernel(const float* __restrict__ att,
                             const float* __restrict__ bias2,
                             float* __restrict__ out) {
    int w = (blockIdx.x * blockDim.x + threadIdx.x) >> 5;
    int lane = threadIdx.x & 31;
    if (w >= NN) return;
    int grp = lane >> 4, sub = lane & 15;
    const bool act = (sub < 10);
    const unsigned gmask = 0xFFFFu << (grp * 16);

    const float4* xl4 = (const float4*)g_xl2;
    float4 xr = make_float4(0.f, 0.f, 0.f, 0.f);
    float4 at = make_float4(0.f, 0.f, 0.f, 0.f);
    if (act) {
        xr = ((const float4*)g_xr2)[w * 10 + sub];
        at = ((const float4*)att)[sub];
    }

    int beg = g_roff[w], end = g_roff[w + 1];

    float mx = -1e30f, den = 0.f;
    float4 ac = make_float4(0.f, 0.f, 0.f, 0.f);

    int e = beg + grp;
    float4 v0 = make_float4(0.f, 0.f, 0.f, 0.f);
    float4 v1 = v0;
    if (e < end && act) v0 = xl4[g_csrc[e] * 10 + sub];
    if (e + 2 < end && act) v1 = xl4[g_csrc[e + 2] * 10 + sub];
    while (e < end) {
        int en = e + 4;
        float4 n0 = make_float4(0.f, 0.f, 0.f, 0.f);
        float4 n1 = n0;
        if (en < end && act) n0 = xl4[g_csrc[en] * 10 + sub];
        if (en + 2 < end && act) n1 = xl4[g_csrc[en + 2] * 10 + sub];
        float pA = lrelu(v0.x + xr.x) * at.x + lrelu(v0.y + xr.y) * at.y
                 + lrelu(v0.z + xr.z) * at.z + lrelu(v0.w + xr.w) * at.w;
        float pB = lrelu(v1.x + xr.x) * at.x + lrelu(v1.y + xr.y) * at.y
                 + lrelu(v1.z + xr.z) * at.z + lrelu(v1.w + xr.w) * at.w;
        pA += __shfl_xor_sync(gmask, pA, 1);
        pB += __shfl_xor_sync(gmask, pB, 1);
        pA += __shfl_xor_sync(gmask, pA, 2);
        pB += __shfl_xor_sync(gmask, pB, 2);
        pA += __shfl_xor_sync(gmask, pA, 4);
        pB += __shfl_xor_sync(gmask, pB, 4);
        pA += __shfl_xor_sync(gmask, pA, 8);
        pB += __shfl_xor_sync(gmask, pB, 8);
        if (e + 2 >= end) pB = -1e30f;  // uniform per group
        float nmx = fmaxf(mx, fmaxf(pA, pB));
        float sc = __expf(mx - nmx);
        float wA = __expf(pA - nmx);
        float wB = __expf(pB - nmx);
        den = den * sc + wA + wB;
        ac.x = fmaf(ac.x, sc, fmaf(wA, v0.x, wB * v1.x));
        ac.y = fmaf(ac.y, sc, fmaf(wA, v0.y, wB * v1.y));
        ac.z = fmaf(ac.z, sc, fmaf(wA, v0.z, wB * v1.z));
        ac.w = fmaf(ac.w, sc, fmaf(wA, v0.w, wB * v1.w));
        mx = nmx;
        e = en;
        v0 = n0; v1 = n1;
    }

    // merge the 2 group states (warp reconverged; full mask safe)
    {
        float omx = __shfl_xor_sync(0xffffffffu, mx, 16);
        float nmx = fmaxf(mx, omx);
        float sc = __expf(mx - nmx);
        den *= sc;
        ac.x *= sc; ac.y *= sc; ac.z *= sc; ac.w *= sc;
        den += __shfl_xor_sync(0xffffffffu, den, 16);
        ac.x += __shfl_xor_sync(0xffffffffu, ac.x, 16);
        ac.y += __shfl_xor_sync(0xffffffffu, ac.y, 16);
        ac.z += __shfl_xor_sync(0xffffffffu, ac.z, 16);
        ac.w += __shfl_xor_sync(0xffffffffu, ac.w, 16);
        mx = nmx;
    }

    float inv = 1.f / den;
    float4 o4 = make_float4(-1e30f, -1e30f, -1e30f, -1e30f);
    if (act) {
        float4 ln = ((const float4*)g_ln2)[w * 10 + sub];
        float4 b4 = ((const float4*)bias2)[sub];
        o4.x = fmaf(ac.x, inv, b4.x + ln.x);
        o4.y = fmaf(ac.y, inv, b4.y + ln.y);
        o4.z = fmaf(ac.z, inv, b4.z + ln.z);
        o4.w = fmaf(ac.w, inv, b4.w + ln.w);
    }
    float m2 = fmaxf(fmaxf(o4.x, o4.y), fmaxf(o4.z, o4.w));
#pragma unroll
    for (int o = 8; o > 0; o >>= 1) m2 = fmaxf(m2, __shfl_xor_sync(0xffffffffu, m2, o));
    float se = act ? (expf(o4.x - m2) + expf(o4.y - m2) + expf(o4.z - m2) + expf(o4.w - m2)) : 0.f;
#pragma unroll
    for (int o = 8; o > 0; o >>= 1) se += __shfl_xor_sync(0xffffffffu, se, o);
    float ls = m2 + logf(se);
    if (act && grp == 0) {
        float4 r;
        r.x = o4.x - ls; r.y = o4.y - ls; r.z = o4.z - ls; r.w = o4.w - ls;
        ((float4*)out)[w * 10 + sub] = r;
    }
}

// ---------------- launch (multi-stream: gemm1 overlaps CSR pipeline) ----------------
extern "C" void kernel_launch(void* const* d_in, const int* in_sizes, int n_in,
                              void* d_out, int out_size) {
    const float* x     = (const float*)d_in[0];
    const void*  ei    = d_in[1];
    const float* W1l   = (const float*)d_in[2];
    const float* b1l   = (const float*)d_in[3];
    const float* W1r   = (const float*)d_in[4];
    const float* b1r   = (const float*)d_in[5];
    const float* att1  = (const float*)d_in[6];
    const float* bias1 = (const float*)d_in[7];
    const float* l1W   = (const float*)d_in[8];
    const float* l1b   = (const float*)d_in[9];
    const float* W2l   = (const float*)d_in[10];
    const float* b2l   = (const float*)d_in[11];
    const float* W2r   = (const float*)d_in[12];
    const float* b2r   = (const float*)d_in[13];
    const float* att2  = (const float*)d_in[14];
    const float* bias2 = (const float*)d_in[15];
    const float* l2W   = (const float*)d_in[16];
    const float* l2b   = (const float*)d_in[17];
    float* out = (float*)d_out;
    int do_pass = (out_size >= NN * CC + 2 * EE) ? 1 : 0;

    static cudaStream_t s2 = nullptr;
    static cudaEvent_t e_fork = nullptr, e_join = nullptr;
    if (!s2) {
        cudaStreamCreateWithFlags(&s2, cudaStreamNonBlocking);
        cudaEventCreateWithFlags(&e_fork, cudaEventDisableTiming);
        cudaEventCreateWithFlags(&e_join, cudaEventDisableTiming);
    }

    cudaEventRecord(e_fork, 0);

    init_kernel<<<NB, 256>>>(ei);                                       // launch 0
    convert_count_kernel<<<(ET + 255) / 256, 256>>>(ei, out, do_pass);  // launch 1
    bsum_kernel<<<NB, 256>>>();                                         // launch 2

    cudaStreamWaitEvent(s2, e_fork, 0);
    gemm1_kernel<<<dim3((NN + 127) / 128, 3), 256, 0, s2>>>(            // launch 3: profiled
        x, W1l, b1l, W1r, b1r, l1W, l1b);
    cudaEventRecord(e_join, s2);

    bscan_kernel<<<1, 256>>>();
    offs_kernel<<<NB, 256>>>();
    scatter_kernel<<<(ET + 255) / 256, 256>>>();

    cudaStreamWaitEvent(0, e_join, 0);
    attn1_kernel<<<(NN * 32 + 255) / 256, 256>>>(att1, bias1);

    gemm2_kernel<<<dim3((NN + 127) / 128, 3), 256>>>(W2l, b2l, W2r, b2r, l2W, l2b);
    attn2_kernel<<<(NN * 32 + 255) / 256, 256>>>(att2, bias2, out);
}

// round 15
// speedup vs baseline: 1.0681x; 1.0681x over previous
#include <cuda_runtime.h>
#include <cuda_fp16.h>
#include <math.h>

#define NN 50000
#define EE 800000
#define ET (EE + NN)
#define FIN 256
#define HH 64
#define CC 40
#define NEG_SLOPE 0.2f
#define NB ((NN + 255) / 256)

typedef unsigned long long u64;

// ---------------- scratch (__device__ globals; no allocation) ----------------
static __device__ int g_is64;
static __device__ int g_src[ET];
static __device__ int g_dst[ET];
static __device__ int g_cnt[NN];
static __device__ int g_roff[NN + 1];
static __device__ int g_cursor[NN];
static __device__ int g_csrc[ET];
static __device__ int g_bsum[NB];
static __device__ int g_bpre[NB];

static __device__ float g_xl1[NN * HH];
static __device__ float g_xr1[NN * HH];
static __device__ float g_ln1[NN * HH];
static __device__ float g_h[NN * HH];

static __device__ float g_xl2[NN * CC];
static __device__ float g_xr2[NN * CC];
static __device__ float g_ln2[NN * CC];

__device__ __forceinline__ float lrelu(float v) { return fmaxf(v, NEG_SLOPE * v); }

__device__ __forceinline__ unsigned f2h2(float lo, float hi) {
    __half2 h = __floats2half2_rn(lo, hi);
    return *reinterpret_cast<unsigned*>(&h);
}

__device__ __forceinline__ void mma_f16(float c[4], unsigned a0, unsigned a1,
                                        unsigned a2, unsigned a3,
                                        unsigned b0, unsigned b1) {
    asm("mma.sync.aligned.m16n8k16.row.col.f32.f16.f16.f32 "
        "{%0,%1,%2,%3}, {%4,%5,%6,%7}, {%8,%9}, {%0,%1,%2,%3};"
        : "+f"(c[0]), "+f"(c[1]), "+f"(c[2]), "+f"(c[3])
        : "r"(a0), "r"(a1), "r"(a2), "r"(a3), "r"(b0), "r"(b1));
}

// ---------------- init: zero counts + edge dtype detect (fused) ----------------
__global__ void init_kernel(const void* edge) {
    int i = blockIdx.x * blockDim.x + threadIdx.x;
    if (i < NN) g_cnt[i] = 0;
    if (blockIdx.x == 0 && threadIdx.x < 32) {
        const int* p = (const int*)edge;
        int ok = 1;
        for (int j = threadIdx.x * 2 + 1; j < 4096; j += 64)
            if (p[j] != 0) ok = 0;
        unsigned b = __ballot_sync(0xffffffffu, ok);
        if (threadIdx.x == 0) g_is64 = (b == 0xffffffffu) ? 1 : 0;
    }
}

// convert edge list (+self loops), histogram dst, emit edge_index passthrough
__global__ void convert_count_kernel(const void* edge, float* __restrict__ out, int do_pass) {
    int t = blockIdx.x * blockDim.x + threadIdx.x;
    if (t >= ET) return;
    int s, d;
    if (t >= EE) {
        s = t - EE; d = t - EE;
    } else if (g_is64) {
        const long long* p = (const long long*)edge;
        s = (int)p[t]; d = (int)p[EE + t];
    } else {
        const int* p = (const int*)edge;
        s = p[t]; d = p[EE + t];
    }
    g_src[t] = s;
    g_dst[t] = d;
    atomicAdd(&g_cnt[d], 1);
    if (do_pass && t < EE) {
        out[NN * CC + t] = (float)s;
        out[NN * CC + EE + t] = (float)d;
    }
}

// ---------------- 3-stage parallel scan over g_cnt ----------------
__global__ void bsum_kernel() {
    __shared__ int ws[8];
    int i = blockIdx.x * 256 + threadIdx.x;
    int lane = threadIdx.x & 31, w = threadIdx.x >> 5;
    int v = (i < NN) ? g_cnt[i] : 0;
#pragma unroll
    for (int o = 16; o > 0; o >>= 1) v += __shfl_xor_sync(0xffffffffu, v, o);
    if (lane == 0) ws[w] = v;
    __syncthreads();
    if (threadIdx.x == 0) {
        int s = 0;
#pragma unroll
        for (int k = 0; k < 8; k++) s += ws[k];
        g_bsum[blockIdx.x] = s;
    }
}

__global__ void bscan_kernel() {  // 1 block, 256 threads; NB <= 256
    __shared__ int ws[8];
    int t = threadIdx.x;
    int lane = t & 31, w = t >> 5;
    int v = (t < NB) ? g_bsum[t] : 0;
    int x = v;
#pragma unroll
    for (int dlt = 1; dlt < 32; dlt <<= 1) {
        int y = __shfl_up_sync(0xffffffffu, x, dlt);
        if (lane >= dlt) x += y;
    }
    if (lane == 31) ws[w] = x;
    __syncthreads();
    if (w == 0 && lane < 8) {
        int s = ws[lane];
#pragma unroll
        for (int dlt = 1; dlt < 8; dlt <<= 1) {
            int y = __shfl_up_sync(0xffu, s, dlt);
            if (lane >= dlt) s += y;
        }
        ws[lane] = s;
    }
    __syncthreads();
    int prefix = (w > 0) ? ws[w - 1] : 0;
    if (t < NB) g_bpre[t] = prefix + x - v;
}

__global__ void offs_kernel() {
    __shared__ int ws[8];
    int i = blockIdx.x * 256 + threadIdx.x;
    int lane = threadIdx.x & 31, w = threadIdx.x >> 5;
    int v = (i < NN) ? g_cnt[i] : 0;
    int x = v;
#pragma unroll
    for (int dlt = 1; dlt < 32; dlt <<= 1) {
        int y = __shfl_up_sync(0xffffffffu, x, dlt);
        if (lane >= dlt) x += y;
    }
    if (lane == 31) ws[w] = x;
    __syncthreads();
    if (w == 0 && lane < 8) {
        int s = ws[lane];
#pragma unroll
        for (int dlt = 1; dlt < 8; dlt <<= 1) {
            int y = __shfl_up_sync(0xffu, s, dlt);
            if (lane >= dlt) s += y;
        }
        ws[lane] = s;
    }
    __syncthreads();
    int prefix = (w > 0) ? ws[w - 1] : 0;
    int excl = g_bpre[blockIdx.x] + prefix + x - v;
    if (i < NN) {
        g_cursor[i] = excl;
        g_roff[i + 1] = excl + v;
    }
    if (i == 0) g_roff[0] = 0;
}

__global__ void scatter_kernel() {
    int t = blockIdx.x * blockDim.x + threadIdx.x;
    if (t >= ET) return;
    int d = g_dst[t];
    int pos = atomicAdd(&g_cursor[d], 1);
    g_csrc[pos] = g_src[t];
}

// ---------------- layer1 node GEMMs: fp16 MMA m16n8k16, R9 shape --------------
// 256 threads = 8 warps; M-tile 128 (16 rows/warp), N = 64, K staged 16.
// As[128][12] half2 (k-pairs), Bs[8][72] half2 (k-pairs) — both conflict-free.
__global__ void __launch_bounds__(256) gemm1_kernel(
    const float* __restrict__ x,
    const float* __restrict__ W1l, const float* __restrict__ b1l,
    const float* __restrict__ W1r, const float* __restrict__ b1r,
    const float* __restrict__ Wn, const float* __restrict__ bn) {
    __shared__ unsigned As[128][12];
    __shared__ unsigned Bs[8][72];
    const int tid = threadIdx.x;
    const int warp = tid >> 5, lane = tid & 31;
    const int gid = lane >> 2, tig = lane & 3;
    const int mat = blockIdx.y;
    const float* W    = (mat == 0) ? W1l : ((mat == 1) ? W1r : Wn);
    const float* bias = (mat == 0) ? b1l : ((mat == 1) ? b1r : bn);
    float* outp       = (mat == 0) ? g_xl1 : ((mat == 1) ? g_xr1 : g_ln1);
    const int m0 = blockIdx.x * 128;
    const int r0 = m0 + warp * 16 + gid, r1 = r0 + 8;

    float acc[8][4];
#pragma unroll
    for (int i = 0; i < 8; i++) {
        acc[i][0] = 0.f; acc[i][1] = 0.f; acc[i][2] = 0.f; acc[i][3] = 0.f;
    }

    for (int ks = 0; ks < FIN; ks += 16) {
        __syncthreads();
        // stage B: 16k x 64n as 8 k-pairs x 64 half2; 128 threads, STS.128 each
        if (tid < 128) {
            int k2 = tid >> 4;            // 0..7
            int c = (tid & 15) * 4;       // 0..60
            float4 w0 = *(const float4*)&W[(ks + 2 * k2) * HH + c];
            float4 w1 = *(const float4*)&W[(ks + 2 * k2 + 1) * HH + c];
            uint4 pk;
            pk.x = f2h2(w0.x, w1.x);
            pk.y = f2h2(w0.y, w1.y);
            pk.z = f2h2(w0.z, w1.z);
            pk.w = f2h2(w0.w, w1.w);
            *(uint4*)&Bs[k2][c] = pk;
        }
        // stage A: 128 rows x 16 k; 512 float4 loads, 2 per thread, STS.64 each
#pragma unroll
        for (int j = 0; j < 2; j++) {
            int f = tid + j * 256;        // 0..511
            int r = f >> 2;
            int c4 = (f & 3) * 4;         // k offset 0,4,8,12
            int rr = m0 + r;
            float4 v = make_float4(0.f, 0.f, 0.f, 0.f);
            if (rr < NN) v = *(const float4*)&x[rr * FIN + ks + c4];
            uint2 pk;
            pk.x = f2h2(v.x, v.y);
            pk.y = f2h2(v.z, v.w);
            *(uint2*)&As[r][c4 >> 1] = pk;
        }
        __syncthreads();

        int ra = warp * 16 + gid, rb = ra + 8;
        unsigned a0 = As[ra][tig];
        unsigned a1 = As[rb][tig];
        unsigned a2 = As[ra][tig + 4];
        unsigned a3 = As[rb][tig + 4];
#pragma unroll
        for (int nc = 0; nc < 8; nc++) {
            unsigned b0 = Bs[tig][nc * 8 + gid];
            unsigned b1 = Bs[tig + 4][nc * 8 + gid];
            mma_f16(acc[nc], a0, a1, a2, a3, b0, b1);
        }
    }

#pragma unroll
    for (int nc = 0; nc < 8; nc++) {
        int n = nc * 8 + tig * 2;
        float b0v = __ldg(&bias[n]);
        float b1v = __ldg(&bias[n + 1]);
        if (r0 < NN)
            *(float2*)&outp[r0 * HH + n] = make_float2(acc[nc][0] + b0v, acc[nc][1] + b1v);
        if (r1 < NN)
            *(float2*)&outp[r1 * HH + n] = make_float2(acc[nc][2] + b0v, acc[nc][3] + b1v);
    }
}

// ---------------- layer1 attention: warp per node, 4 edge-groups of 8 lanes ----------------
// (R13 version: single-edge + 1-deep prefetch, group masks in-loop)
__global__ void attn1_kernel(const float* __restrict__ att,
                             const float* __restrict__ bias1) {
    int w = (blockIdx.x * blockDim.x + threadIdx.x) >> 5;
    int lane = threadIdx.x & 31;
    if (w >= NN) return;
    int grp = lane >> 3, sub = lane & 7;
    const unsigned gmask = 0xFFu << (grp * 8);

    const float4* xl4 = (const float4*)g_xl1;
    float4 xrA = ((const float4*)g_xr1)[w * 16 + sub * 2];
    float4 xrB = ((const float4*)g_xr1)[w * 16 + sub * 2 + 1];
    float4 atA = ((const float4*)att)[sub * 2];
    float4 atB = ((const float4*)att)[sub * 2 + 1];

    int beg = g_roff[w], end = g_roff[w + 1];

    float mx = -1e30f, den = 0.f;
    float4 aA = make_float4(0.f, 0.f, 0.f, 0.f);
    float4 aB = make_float4(0.f, 0.f, 0.f, 0.f);

    int e = beg + grp;
    float4 vA = make_float4(0.f, 0.f, 0.f, 0.f);
    float4 vB = make_float4(0.f, 0.f, 0.f, 0.f);
    if (e < end) {
        int s = g_csrc[e];
        vA = xl4[s * 16 + sub * 2];
        vB = xl4[s * 16 + sub * 2 + 1];
    }
    while (e < end) {
        int en = e + 4;
        float4 vA2 = make_float4(0.f, 0.f, 0.f, 0.f);
        float4 vB2 = make_float4(0.f, 0.f, 0.f, 0.f);
        if (en < end) {
            int s2 = g_csrc[en];
            vA2 = xl4[s2 * 16 + sub * 2];
            vB2 = xl4[s2 * 16 + sub * 2 + 1];
        }
        float p = lrelu(vA.x + xrA.x) * atA.x + lrelu(vA.y + xrA.y) * atA.y
                + lrelu(vA.z + xrA.z) * atA.z + lrelu(vA.w + xrA.w) * atA.w
                + lrelu(vB.x + xrB.x) * atB.x + lrelu(vB.y + xrB.y) * atB.y
                + lrelu(vB.z + xrB.z) * atB.z + lrelu(vB.w + xrB.w) * atB.w;
        p += __shfl_xor_sync(gmask, p, 1);
        p += __shfl_xor_sync(gmask, p, 2);
        p += __shfl_xor_sync(gmask, p, 4);
        float nmx = fmaxf(mx, p);
        float sc = __expf(mx - nmx);
        float ww = __expf(p - nmx);
        den = fmaf(den, sc, ww);
        aA.x = fmaf(aA.x, sc, ww * vA.x); aA.y = fmaf(aA.y, sc, ww * vA.y);
        aA.z = fmaf(aA.z, sc, ww * vA.z); aA.w = fmaf(aA.w, sc, ww * vA.w);
        aB.x = fmaf(aB.x, sc, ww * vB.x); aB.y = fmaf(aB.y, sc, ww * vB.y);
        aB.z = fmaf(aB.z, sc, ww * vB.z); aB.w = fmaf(aB.w, sc, ww * vB.w);
        mx = nmx;
        e = en; vA = vA2; vB = vB2;
    }

#pragma unroll
    for (int msk = 8; msk <= 16; msk <<= 1) {
        float omx = __shfl_xor_sync(0xffffffffu, mx, msk);
        float nmx = fmaxf(mx, omx);
        float sc = __expf(mx - nmx);
        den *= sc;
        aA.x *= sc; aA.y *= sc; aA.z *= sc; aA.w *= sc;
        aB.x *= sc; aB.y *= sc; aB.z *= sc; aB.w *= sc;
        den += __shfl_xor_sync(0xffffffffu, den, msk);
        aA.x += __shfl_xor_sync(0xffffffffu, aA.x, msk);
        aA.y += __shfl_xor_sync(0xffffffffu, aA.y, msk);
        aA.z += __shfl_xor_sync(0xffffffffu, aA.z, msk);
        aA.w += __shfl_xor_sync(0xffffffffu, aA.w, msk);
        aB.x += __shfl_xor_sync(0xffffffffu, aB.x, msk);
        aB.y += __shfl_xor_sync(0xffffffffu, aB.y, msk);
        aB.z += __shfl_xor_sync(0xffffffffu, aB.z, msk);
        aB.w += __shfl_xor_sync(0xffffffffu, aB.w, msk);
        mx = nmx;
    }

    if (grp == 0) {
        float inv = 1.f / den;
        float4 lnA = ((const float4*)g_ln1)[w * 16 + sub * 2];
        float4 lnB = ((const float4*)g_ln1)[w * 16 + sub * 2 + 1];
        float4 bA = ((const float4*)bias1)[sub * 2];
        float4 bB = ((const float4*)bias1)[sub * 2 + 1];
        float4 hA, hB;
        hA.x = fmaxf(fmaf(aA.x, inv, bA.x + lnA.x), 0.f);
        hA.y = fmaxf(fmaf(aA.y, inv, bA.y + lnA.y), 0.f);
        hA.z = fmaxf(fmaf(aA.z, inv, bA.z + lnA.z), 0.f);
        hA.w = fmaxf(fmaf(aA.w, inv, bA.w + lnA.w), 0.f);
        hB.x = fmaxf(fmaf(aB.x, inv, bB.x + lnB.x), 0.f);
        hB.y = fmaxf(fmaf(aB.y, inv, bB.y + lnB.y), 0.f);
        hB.z = fmaxf(fmaf(aB.z, inv, bB.z + lnB.z), 0.f);
        hB.w = fmaxf(fmaf(aB.w, inv, bB.w + lnB.w), 0.f);
        ((float4*)g_h)[w * 16 + sub * 2] = hA;
        ((float4*)g_h)[w * 16 + sub * 2 + 1] = hB;
    }
}

// ---------------- layer2 node GEMMs: fp16 MMA, R9 shape, CC=40 = 5 n8 blocks ----
__global__ void __launch_bounds__(256) gemm2_kernel(
    const float* __restrict__ Wl, const float* __restrict__ bl,
    const float* __restrict__ Wr, const float* __restrict__ br,
    const float* __restrict__ Wn, const float* __restrict__ bn) {
    __shared__ unsigned As[128][12];
    __shared__ unsigned Bs[8][40];  // stride 40: banks tig*8+gid distinct
    const int tid = threadIdx.x;
    const int warp = tid >> 5, lane = tid & 31;
    const int gid = lane >> 2, tig = lane & 3;
    const int mat = blockIdx.y;
    const float* W    = (mat == 0) ? Wl : ((mat == 1) ? Wr : Wn);
    const float* bias = (mat == 0) ? bl : ((mat == 1) ? br : bn);
    float* outp       = (mat == 0) ? g_xl2 : ((mat == 1) ? g_xr2 : g_ln2);
    const int m0 = blockIdx.x * 128;
    const int r0 = m0 + warp * 16 + gid, r1 = r0 + 8;

    float acc[5][4];
#pragma unroll
    for (int i = 0; i < 5; i++) {
        acc[i][0] = 0.f; acc[i][1] = 0.f; acc[i][2] = 0.f; acc[i][3] = 0.f;
    }

    for (int ks = 0; ks < HH; ks += 16) {
        __syncthreads();
        // stage B: 8 k-pairs x 40 half2 = 320 words
#pragma unroll
        for (int j = 0; j < 2; j++) {
            int f = tid + j * 256;
            if (f < 320) {
                int k2 = f / 40;
                int c = f - k2 * 40;
                float lo = __ldg(&W[(ks + 2 * k2) * CC + c]);
                float hi = __ldg(&W[(ks + 2 * k2 + 1) * CC + c]);
                Bs[k2][c] = f2h2(lo, hi);
            }
        }
        // stage A (g_h): 128 rows x 16 k; 2 float4 per thread
#pragma unroll
        for (int j = 0; j < 2; j++) {
            int f = tid + j * 256;
            int r = f >> 2;
            int c4 = (f & 3) * 4;
            int rr = m0 + r;
            float4 v = make_float4(0.f, 0.f, 0.f, 0.f);
            if (rr < NN) v = *(const float4*)&g_h[rr * HH + ks + c4];
            uint2 pk;
            pk.x = f2h2(v.x, v.y);
            pk.y = f2h2(v.z, v.w);
            *(uint2*)&As[r][c4 >> 1] = pk;
        }
        __syncthreads();

        int ra = warp * 16 + gid, rb = ra + 8;
        unsigned a0 = As[ra][tig];
        unsigned a1 = As[rb][tig];
        unsigned a2 = As[ra][tig + 4];
        unsigned a3 = As[rb][tig + 4];
#pragma unroll
        for (int nc = 0; nc < 5; nc++) {
            unsigned b0 = Bs[tig][nc * 8 + gid];
            unsigned b1 = Bs[tig + 4][nc * 8 + gid];
            mma_f16(acc[nc], a0, a1, a2, a3, b0, b1);
        }
    }

#pragma unroll
    for (int nc = 0; nc < 5; nc++) {
        int n = nc * 8 + tig * 2;
        float b0v = __ldg(&bias[n]);
        float b1v = __ldg(&bias[n + 1]);
        if (r0 < NN)
            *(float2*)&outp[r0 * CC + n] = make_float2(acc[nc][0] + b0v, acc[nc][1] + b1v);
        if (r1 < NN)
            *(float2*)&outp[r1 * CC + n] = make_float2(acc[nc][2] + b0v, acc[nc][3] + b1v);
    }
}

// ---------------- layer2 attention + log_softmax (R13 version) ----------------
__global__ void attn2_kernel(const float* __restrict__ att,
                             const float* __restrict__ bias2,
                             float* __restrict__ out) {
    int w = (blockIdx.x * blockDim.x + threadIdx.x) >> 5;
    int lane = threadIdx.x & 31;
    if (w >= NN) return;
    int grp = lane >> 4, sub = lane & 15;
    const bool act = (sub < 10);
    const unsigned gmask = 0xFFFFu << (grp * 16);

    const float4* xl4 = (const float4*)g_xl2;
    float4 xr = make_float4(0.f, 0.f, 0.f, 0.f);
    float4 at = make_float4(0.f, 0.f, 0.f, 0.f);
    if (act) {
        xr = ((const float4*)g_xr2)[w * 10 + sub];
        at = ((const float4*)att)[sub];
    }

    int beg = g_roff[w], end = g_roff[w + 1];

    float mx = -1e30f, den = 0.f;
    float4 ac = make_float4(0.f, 0.f, 0.f, 0.f);

    int e = beg + grp;
    float4 v = make_float4(0.f, 0.f, 0.f, 0.f);
    if (e < end && act) v = xl4[g_csrc[e] * 10 + sub];
    while (e < end) {
        int en = e + 2;
        float4 v2 = make_float4(0.f, 0.f, 0.f, 0.f);
        if (en < end && act) v2 = xl4[g_csrc[en] * 10 + sub];
        float p = lrelu(v.x + xr.x) * at.x + lrelu(v.y + xr.y) * at.y
                + lrelu(v.z + xr.z) * at.z + lrelu(v.w + xr.w) * at.w;
        p += __shfl_xor_sync(gmask, p, 1);
        p += __shfl_xor_sync(gmask, p, 2);
        p += __shfl_xor_sync(gmask, p, 4);
        p += __shfl_xor_sync(gmask, p, 8);
        float nmx = fmaxf(mx, p);
        float sc = __expf(mx - nmx);
        float ww = __expf(p - nmx);
        den = fmaf(den, sc, ww);
        ac.x = fmaf(ac.x, sc, ww * v.x); ac.y = fmaf(ac.y, sc, ww * v.y);
        ac.z = fmaf(ac.z, sc, ww * v.z); ac.w = fmaf(ac.w, sc, ww * v.w);
        mx = nmx;
        e = en; v = v2;
    }

    {
        float omx = __shfl_xor_sync(0xffffffffu, mx, 16);
        float nmx = fmaxf(mx, omx);
        float sc = __expf(mx - nmx);
        den *= sc;
        ac.x *= sc; ac.y *= sc; ac.z *= sc; ac.w *= sc;
        den += __shfl_xor_sync(0xffffffffu, den, 16);
        ac.x += __shfl_xor_sync(0xffffffffu, ac.x, 16);
        ac.y += __shfl_xor_sync(0xffffffffu, ac.y, 16);
        ac.z += __shfl_xor_sync(0xffffffffu, ac.z, 16);
        ac.w += __shfl_xor_sync(0xffffffffu, ac.w, 16);
        mx = nmx;
    }

    float inv = 1.f / den;
    float4 o4 = make_float4(-1e30f, -1e30f, -1e30f, -1e30f);
    if (act) {
        float4 ln = ((const float4*)g_ln2)[w * 10 + sub];
        float4 b4 = ((const float4*)bias2)[sub];
        o4.x = fmaf(ac.x, inv, b4.x + ln.x);
        o4.y = fmaf(ac.y, inv, b4.y + ln.y);
        o4.z = fmaf(ac.z, inv, b4.z + ln.z);
        o4.w = fmaf(ac.w, inv, b4.w + ln.w);
    }
    float m2 = fmaxf(fmaxf(o4.x, o4.y), fmaxf(o4.z, o4.w));
#pragma unroll
    for (int o = 8; o > 0; o >>= 1) m2 = fmaxf(m2, __shfl_xor_sync(0xffffffffu, m2, o));
    float se = act ? (expf(o4.x - m2) + expf(o4.y - m2) + expf(o4.z - m2) + expf(o4.w - m2)) : 0.f;
#pragma unroll
    for (int o = 8; o > 0; o >>= 1) se += __shfl_xor_sync(0xffffffffu, se, o);
    float ls = m2 + logf(se);
    if (act && grp == 0) {
        float4 r;
        r.x = o4.x - ls; r.y = o4.y - ls; r.z = o4.z - ls; r.w = o4.w - ls;
        ((float4*)out)[w * 10 + sub] = r;
    }
}

// ---------------- launch (multi-stream: gemm1 overlaps CSR pipeline) ----------------
extern "C" void kernel_launch(void* const* d_in, const int* in_sizes, int n_in,
                              void* d_out, int out_size) {
    const float* x     = (const float*)d_in[0];
    const void*  ei    = d_in[1];
    const float* W1l   = (const float*)d_in[2];
    const float* b1l   = (const float*)d_in[3];
    const float* W1r   = (const float*)d_in[4];
    const float* b1r   = (const float*)d_in[5];
    const float* att1  = (const float*)d_in[6];
    const float* bias1 = (const float*)d_in[7];
    const float* l1W   = (const float*)d_in[8];
    const float* l1b   = (const float*)d_in[9];
    const float* W2l   = (const float*)d_in[10];
    const float* b2l   = (const float*)d_in[11];
    const float* W2r   = (const float*)d_in[12];
    const float* b2r   = (const float*)d_in[13];
    const float* att2  = (const float*)d_in[14];
    const float* bias2 = (const float*)d_in[15];
    const float* l2W   = (const float*)d_in[16];
    const float* l2b   = (const float*)d_in[17];
    float* out = (float*)d_out;
    int do_pass = (out_size >= NN * CC + 2 * EE) ? 1 : 0;

    static cudaStream_t s2 = nullptr;
    static cudaEvent_t e_fork = nullptr, e_join = nullptr;
    if (!s2) {
        cudaStreamCreateWithFlags(&s2, cudaStreamNonBlocking);
        cudaEventCreateWithFlags(&e_fork, cudaEventDisableTiming);
        cudaEventCreateWithFlags(&e_join, cudaEventDisableTiming);
    }

    cudaEventRecord(e_fork, 0);

    init_kernel<<<NB, 256>>>(ei);                                       // launch 0
    convert_count_kernel<<<(ET + 255) / 256, 256>>>(ei, out, do_pass);  // launch 1
    bsum_kernel<<<NB, 256>>>();                                         // launch 2

    cudaStreamWaitEvent(s2, e_fork, 0);
    gemm1_kernel<<<dim3((NN + 127) / 128, 3), 256, 0, s2>>>(            // launch 3: profiled
        x, W1l, b1l, W1r, b1r, l1W, l1b);
    cudaEventRecord(e_join, s2);

    bscan_kernel<<<1, 256>>>();
    offs_kernel<<<NB, 256>>>();
    scatter_kernel<<<(ET + 255) / 256, 256>>>();

    cudaStreamWaitEvent(0, e_join, 0);
    attn1_kernel<<<(NN * 32 + 255) / 256, 256>>>(att1, bias1);

    gemm2_kernel<<<dim3((NN + 127) / 128, 3), 256>>>(W2l, b2l, W2r, b2r, l2W, l2b);
    attn2_kernel<<<(NN * 32 + 255) / 256, 256>>>(att2, bias2, out);
}

// round 17
// speedup vs baseline: 1.0803x; 1.0114x over previous
#include <cuda_runtime.h>
#include <cuda_fp16.h>
#include <math.h>

#define NN 50000
#define EE 800000
#define ET (EE + NN)
#define FIN 256
#define HH 64
#define CC 40
#define NEG_SLOPE 0.2f
#define NB ((NN + 255) / 256)

typedef unsigned long long u64;

// ---------------- scratch (__device__ globals; no allocation) ----------------
static __device__ int g_is64;
static __device__ int g_src[ET];
static __device__ int g_dst[ET];
static __device__ int g_cnt[NN];
static __device__ int g_roff[NN + 1];
static __device__ int g_cursor[NN];
static __device__ int g_csrc[ET];
static __device__ int g_bsum[NB];
static __device__ int g_bpre[NB];

static __device__ uint4 g_xl1h[NN * 8];   // xl1 in fp16: 64 halves/row = 8 uint4
static __device__ float g_xr1[NN * HH];
static __device__ float g_ln1[NN * HH];
static __device__ float g_h[NN * HH];

static __device__ uint2 g_xl2h[NN * 10];  // xl2 in fp16: 40 halves/row = 10 uint2
static __device__ float g_xr2[NN * CC];
static __device__ float g_ln2[NN * CC];

__device__ __forceinline__ float lrelu(float v) { return fmaxf(v, NEG_SLOPE * v); }

__device__ __forceinline__ unsigned f2h2(float lo, float hi) {
    __half2 h = __floats2half2_rn(lo, hi);
    return *reinterpret_cast<unsigned*>(&h);
}

__device__ __forceinline__ void mma_f16(float c[4], unsigned a0, unsigned a1,
                                        unsigned a2, unsigned a3,
                                        unsigned b0, unsigned b1) {
    asm("mma.sync.aligned.m16n8k16.row.col.f32.f16.f16.f32 "
        "{%0,%1,%2,%3}, {%4,%5,%6,%7}, {%8,%9}, {%0,%1,%2,%3};"
        : "+f"(c[0]), "+f"(c[1]), "+f"(c[2]), "+f"(c[3])
        : "r"(a0), "r"(a1), "r"(a2), "r"(a3), "r"(b0), "r"(b1));
}

// ---------------- init: zero counts + edge dtype detect (fused) ----------------
__global__ void init_kernel(const void* edge) {
    int i = blockIdx.x * blockDim.x + threadIdx.x;
    if (i < NN) g_cnt[i] = 0;
    if (blockIdx.x == 0 && threadIdx.x < 32) {
        const int* p = (const int*)edge;
        int ok = 1;
        for (int j = threadIdx.x * 2 + 1; j < 4096; j += 64)
            if (p[j] != 0) ok = 0;
        unsigned b = __ballot_sync(0xffffffffu, ok);
        if (threadIdx.x == 0) g_is64 = (b == 0xffffffffu) ? 1 : 0;
    }
}

// convert edge list (+self loops), histogram dst, emit edge_index passthrough
__global__ void convert_count_kernel(const void* edge, float* __restrict__ out, int do_pass) {
    int t = blockIdx.x * blockDim.x + threadIdx.x;
    if (t >= ET) return;
    int s, d;
    if (t >= EE) {
        s = t - EE; d = t - EE;
    } else if (g_is64) {
        const long long* p = (const long long*)edge;
        s = (int)p[t]; d = (int)p[EE + t];
    } else {
        const int* p = (const int*)edge;
        s = p[t]; d = p[EE + t];
    }
    g_src[t] = s;
    g_dst[t] = d;
    atomicAdd(&g_cnt[d], 1);
    if (do_pass && t < EE) {
        out[NN * CC + t] = (float)s;
        out[NN * CC + EE + t] = (float)d;
    }
}

// ---------------- 3-stage parallel scan over g_cnt ----------------
__global__ void bsum_kernel() {
    __shared__ int ws[8];
    int i = blockIdx.x * 256 + threadIdx.x;
    int lane = threadIdx.x & 31, w = threadIdx.x >> 5;
    int v = (i < NN) ? g_cnt[i] : 0;
#pragma unroll
    for (int o = 16; o > 0; o >>= 1) v += __shfl_xor_sync(0xffffffffu, v, o);
    if (lane == 0) ws[w] = v;
    __syncthreads();
    if (threadIdx.x == 0) {
        int s = 0;
#pragma unroll
        for (int k = 0; k < 8; k++) s += ws[k];
        g_bsum[blockIdx.x] = s;
    }
}

__global__ void bscan_kernel() {  // 1 block, 256 threads; NB <= 256
    __shared__ int ws[8];
    int t = threadIdx.x;
    int lane = t & 31, w = t >> 5;
    int v = (t < NB) ? g_bsum[t] : 0;
    int x = v;
#pragma unroll
    for (int dlt = 1; dlt < 32; dlt <<= 1) {
        int y = __shfl_up_sync(0xffffffffu, x, dlt);
        if (lane >= dlt) x += y;
    }
    if (lane == 31) ws[w] = x;
    __syncthreads();
    if (w == 0 && lane < 8) {
        int s = ws[lane];
#pragma unroll
        for (int dlt = 1; dlt < 8; dlt <<= 1) {
            int y = __shfl_up_sync(0xffu, s, dlt);
            if (lane >= dlt) s += y;
        }
        ws[lane] = s;
    }
    __syncthreads();
    int prefix = (w > 0) ? ws[w - 1] : 0;
    if (t < NB) g_bpre[t] = prefix + x - v;
}

__global__ void offs_kernel() {
    __shared__ int ws[8];
    int i = blockIdx.x * 256 + threadIdx.x;
    int lane = threadIdx.x & 31, w = threadIdx.x >> 5;
    int v = (i < NN) ? g_cnt[i] : 0;
    int x = v;
#pragma unroll
    for (int dlt = 1; dlt < 32; dlt <<= 1) {
        int y = __shfl_up_sync(0xffffffffu, x, dlt);
        if (lane >= dlt) x += y;
    }
    if (lane == 31) ws[w] = x;
    __syncthreads();
    if (w == 0 && lane < 8) {
        int s = ws[lane];
#pragma unroll
        for (int dlt = 1; dlt < 8; dlt <<= 1) {
            int y = __shfl_up_sync(0xffu, s, dlt);
            if (lane >= dlt) s += y;
        }
        ws[lane] = s;
    }
    __syncthreads();
    int prefix = (w > 0) ? ws[w - 1] : 0;
    int excl = g_bpre[blockIdx.x] + prefix + x - v;
    if (i < NN) {
        g_cursor[i] = excl;
        g_roff[i + 1] = excl + v;
    }
    if (i == 0) g_roff[0] = 0;
}

__global__ void scatter_kernel() {
    int t = blockIdx.x * blockDim.x + threadIdx.x;
    if (t >= ET) return;
    int d = g_dst[t];
    int pos = atomicAdd(&g_cursor[d], 1);
    g_csrc[pos] = g_src[t];
}

// ---------------- layer1 node GEMMs: fp16 MMA m16n8k16, R9 shape --------------
// mat 0 (xl) writes fp16 output; mats 1,2 write fp32.
__global__ void __launch_bounds__(256) gemm1_kernel(
    const float* __restrict__ x,
    const float* __restrict__ W1l, const float* __restrict__ b1l,
    const float* __restrict__ W1r, const float* __restrict__ b1r,
    const float* __restrict__ Wn, const float* __restrict__ bn) {
    __shared__ unsigned As[128][12];
    __shared__ unsigned Bs[8][72];
    const int tid = threadIdx.x;
    const int warp = tid >> 5, lane = tid & 31;
    const int gid = lane >> 2, tig = lane & 3;
    const int mat = blockIdx.y;
    const float* W    = (mat == 0) ? W1l : ((mat == 1) ? W1r : Wn);
    const float* bias = (mat == 0) ? b1l : ((mat == 1) ? b1r : bn);
    float* outp       = (mat == 1) ? g_xr1 : g_ln1;
    const int m0 = blockIdx.x * 128;
    const int r0 = m0 + warp * 16 + gid, r1 = r0 + 8;

    float acc[8][4];
#pragma unroll
    for (int i = 0; i < 8; i++) {
        acc[i][0] = 0.f; acc[i][1] = 0.f; acc[i][2] = 0.f; acc[i][3] = 0.f;
    }

    for (int ks = 0; ks < FIN; ks += 16) {
        __syncthreads();
        if (tid < 128) {
            int k2 = tid >> 4;
            int c = (tid & 15) * 4;
            float4 w0 = *(const float4*)&W[(ks + 2 * k2) * HH + c];
            float4 w1 = *(const float4*)&W[(ks + 2 * k2 + 1) * HH + c];
            uint4 pk;
            pk.x = f2h2(w0.x, w1.x);
            pk.y = f2h2(w0.y, w1.y);
            pk.z = f2h2(w0.z, w1.z);
            pk.w = f2h2(w0.w, w1.w);
            *(uint4*)&Bs[k2][c] = pk;
        }
#pragma unroll
        for (int j = 0; j < 2; j++) {
            int f = tid + j * 256;
            int r = f >> 2;
            int c4 = (f & 3) * 4;
            int rr = m0 + r;
            float4 v = make_float4(0.f, 0.f, 0.f, 0.f);
            if (rr < NN) v = *(const float4*)&x[rr * FIN + ks + c4];
            uint2 pk;
            pk.x = f2h2(v.x, v.y);
            pk.y = f2h2(v.z, v.w);
            *(uint2*)&As[r][c4 >> 1] = pk;
        }
        __syncthreads();

        int ra = warp * 16 + gid, rb = ra + 8;
        unsigned a0 = As[ra][tig];
        unsigned a1 = As[rb][tig];
        unsigned a2 = As[ra][tig + 4];
        unsigned a3 = As[rb][tig + 4];
#pragma unroll
        for (int nc = 0; nc < 8; nc++) {
            unsigned b0 = Bs[tig][nc * 8 + gid];
            unsigned b1 = Bs[tig + 4][nc * 8 + gid];
            mma_f16(acc[nc], a0, a1, a2, a3, b0, b1);
        }
    }

    if (mat == 0) {
        unsigned* oh = (unsigned*)g_xl1h;  // half2 view: index (r*HH+n)/2
#pragma unroll
        for (int nc = 0; nc < 8; nc++) {
            int n = nc * 8 + tig * 2;
            float b0v = __ldg(&bias[n]);
            float b1v = __ldg(&bias[n + 1]);
            if (r0 < NN) oh[(r0 * HH + n) >> 1] = f2h2(acc[nc][0] + b0v, acc[nc][1] + b1v);
            if (r1 < NN) oh[(r1 * HH + n) >> 1] = f2h2(acc[nc][2] + b0v, acc[nc][3] + b1v);
        }
    } else {
#pragma unroll
        for (int nc = 0; nc < 8; nc++) {
            int n = nc * 8 + tig * 2;
            float b0v = __ldg(&bias[n]);
            float b1v = __ldg(&bias[n + 1]);
            if (r0 < NN)
                *(float2*)&outp[r0 * HH + n] = make_float2(acc[nc][0] + b0v, acc[nc][1] + b1v);
            if (r1 < NN)
                *(float2*)&outp[r1 * HH + n] = make_float2(acc[nc][2] + b0v, acc[nc][3] + b1v);
        }
    }
}

// ---------------- layer1 attention: warp/node, 4 groups, fp16 xl gathers ----
__global__ void attn1_kernel(const float* __restrict__ att,
                             const float* __restrict__ bias1) {
    int w = (blockIdx.x * blockDim.x + threadIdx.x) >> 5;
    int lane = threadIdx.x & 31;
    if (w >= NN) return;
    int grp = lane >> 3, sub = lane & 7;
    const unsigned gmask = 0xFFu << (grp * 8);

    float4 xrA = ((const float4*)g_xr1)[w * 16 + sub * 2];
    float4 xrB = ((const float4*)g_xr1)[w * 16 + sub * 2 + 1];
    float4 atA = ((const float4*)att)[sub * 2];
    float4 atB = ((const float4*)att)[sub * 2 + 1];

    int beg = g_roff[w], end = g_roff[w + 1];

    float mx = -1e30f, den = 0.f;
    float4 aA = make_float4(0.f, 0.f, 0.f, 0.f);
    float4 aB = make_float4(0.f, 0.f, 0.f, 0.f);

    int e = beg + grp;
    uint4 hv = make_uint4(0u, 0u, 0u, 0u);
    if (e < end) hv = g_xl1h[g_csrc[e] * 8 + sub];
    while (e < end) {
        int en = e + 4;
        uint4 hv2 = make_uint4(0u, 0u, 0u, 0u);
        if (en < end) hv2 = g_xl1h[g_csrc[en] * 8 + sub];
        // unpack 8 halves -> vA (dims 0-3), vB (dims 4-7)
        float2 p0 = __half22float2(*(__half2*)&hv.x);
        float2 p1 = __half22float2(*(__half2*)&hv.y);
        float2 p2 = __half22float2(*(__half2*)&hv.z);
        float2 p3 = __half22float2(*(__half2*)&hv.w);
        float4 vA = make_float4(p0.x, p0.y, p1.x, p1.y);
        float4 vB = make_float4(p2.x, p2.y, p3.x, p3.y);
        float p = lrelu(vA.x + xrA.x) * atA.x + lrelu(vA.y + xrA.y) * atA.y
                + lrelu(vA.z + xrA.z) * atA.z + lrelu(vA.w + xrA.w) * atA.w
                + lrelu(vB.x + xrB.x) * atB.x + lrelu(vB.y + xrB.y) * atB.y
                + lrelu(vB.z + xrB.z) * atB.z + lrelu(vB.w + xrB.w) * atB.w;
        p += __shfl_xor_sync(gmask, p, 1);
        p += __shfl_xor_sync(gmask, p, 2);
        p += __shfl_xor_sync(gmask, p, 4);
        float nmx = fmaxf(mx, p);
        float sc = __expf(mx - nmx);
        float ww = __expf(p - nmx);
        den = fmaf(den, sc, ww);
        aA.x = fmaf(aA.x, sc, ww * vA.x); aA.y = fmaf(aA.y, sc, ww * vA.y);
        aA.z = fmaf(aA.z, sc, ww * vA.z); aA.w = fmaf(aA.w, sc, ww * vA.w);
        aB.x = fmaf(aB.x, sc, ww * vB.x); aB.y = fmaf(aB.y, sc, ww * vB.y);
        aB.z = fmaf(aB.z, sc, ww * vB.z); aB.w = fmaf(aB.w, sc, ww * vB.w);
        mx = nmx;
        e = en; hv = hv2;
    }

#pragma unroll
    for (int msk = 8; msk <= 16; msk <<= 1) {
        float omx = __shfl_xor_sync(0xffffffffu, mx, msk);
        float nmx = fmaxf(mx, omx);
        float sc = __expf(mx - nmx);
        den *= sc;
        aA.x *= sc; aA.y *= sc; aA.z *= sc; aA.w *= sc;
        aB.x *= sc; aB.y *= sc; aB.z *= sc; aB.w *= sc;
        den += __shfl_xor_sync(0xffffffffu, den, msk);
        aA.x += __shfl_xor_sync(0xffffffffu, aA.x, msk);
        aA.y += __shfl_xor_sync(0xffffffffu, aA.y, msk);
        aA.z += __shfl_xor_sync(0xffffffffu, aA.z, msk);
        aA.w += __shfl_xor_sync(0xffffffffu, aA.w, msk);
        aB.x += __shfl_xor_sync(0xffffffffu, aB.x, msk);
        aB.y += __shfl_xor_sync(0xffffffffu, aB.y, msk);
        aB.z += __shfl_xor_sync(0xffffffffu, aB.z, msk);
        aB.w += __shfl_xor_sync(0xffffffffu, aB.w, msk);
        mx = nmx;
    }

    if (grp == 0) {
        float inv = 1.f / den;
        float4 lnA = ((const float4*)g_ln1)[w * 16 + sub * 2];
        float4 lnB = ((const float4*)g_ln1)[w * 16 + sub * 2 + 1];
        float4 bA = ((const float4*)bias1)[sub * 2];
        float4 bB = ((const float4*)bias1)[sub * 2 + 1];
        float4 hA, hB;
        hA.x = fmaxf(fmaf(aA.x, inv, bA.x + lnA.x), 0.f);
        hA.y = fmaxf(fmaf(aA.y, inv, bA.y + lnA.y), 0.f);
        hA.z = fmaxf(fmaf(aA.z, inv, bA.z + lnA.z), 0.f);
        hA.w = fmaxf(fmaf(aA.w, inv, bA.w + lnA.w), 0.f);
        hB.x = fmaxf(fmaf(aB.x, inv, bB.x + lnB.x), 0.f);
        hB.y = fmaxf(fmaf(aB.y, inv, bB.y + lnB.y), 0.f);
        hB.z = fmaxf(fmaf(aB.z, inv, bB.z + lnB.z), 0.f);
        hB.w = fmaxf(fmaf(aB.w, inv, bB.w + lnB.w), 0.f);
        ((float4*)g_h)[w * 16 + sub * 2] = hA;
        ((float4*)g_h)[w * 16 + sub * 2 + 1] = hB;
    }
}

// ---------------- layer2 node GEMMs: fp16 MMA, R9 shape, CC=40 -----------------
__global__ void __launch_bounds__(256) gemm2_kernel(
    const float* __restrict__ Wl, const float* __restrict__ bl,
    const float* __restrict__ Wr, const float* __restrict__ br,
    const float* __restrict__ Wn, const float* __restrict__ bn) {
    __shared__ unsigned As[128][12];
    __shared__ unsigned Bs[8][40];
    const int tid = threadIdx.x;
    const int warp = tid >> 5, lane = tid & 31;
    const int gid = lane >> 2, tig = lane & 3;
    const int mat = blockIdx.y;
    const float* W    = (mat == 0) ? Wl : ((mat == 1) ? Wr : Wn);
    const float* bias = (mat == 0) ? bl : ((mat == 1) ? br : bn);
    float* outp       = (mat == 1) ? g_xr2 : g_ln2;
    const int m0 = blockIdx.x * 128;
    const int r0 = m0 + warp * 16 + gid, r1 = r0 + 8;

    float acc[5][4];
#pragma unroll
    for (int i = 0; i < 5; i++) {
        acc[i][0] = 0.f; acc[i][1] = 0.f; acc[i][2] = 0.f; acc[i][3] = 0.f;
    }

    for (int ks = 0; ks < HH; ks += 16) {
        __syncthreads();
#pragma unroll
        for (int j = 0; j < 2; j++) {
            int f = tid + j * 256;
            if (f < 320) {
                int k2 = f / 40;
                int c = f - k2 * 40;
                float lo = __ldg(&W[(ks + 2 * k2) * CC + c]);
                float hi = __ldg(&W[(ks + 2 * k2 + 1) * CC + c]);
                Bs[k2][c] = f2h2(lo, hi);
            }
        }
#pragma unroll
        for (int j = 0; j < 2; j++) {
            int f = tid + j * 256;
            int r = f >> 2;
            int c4 = (f & 3) * 4;
            int rr = m0 + r;
            float4 v = make_float4(0.f, 0.f, 0.f, 0.f);
            if (rr < NN) v = *(const float4*)&g_h[rr * HH + ks + c4];
            uint2 pk;
            pk.x = f2h2(v.x, v.y);
            pk.y = f2h2(v.z, v.w);
            *(uint2*)&As[r][c4 >> 1] = pk;
        }
        __syncthreads();

        int ra = warp * 16 + gid, rb = ra + 8;
        unsigned a0 = As[ra][tig];
        unsigned a1 = As[rb][tig];
        unsigned a2 = As[ra][tig + 4];
        unsigned a3 = As[rb][tig + 4];
#pragma unroll
        for (int nc = 0; nc < 5; nc++) {
            unsigned b0 = Bs[tig][nc * 8 + gid];
            unsigned b1 = Bs[tig + 4][nc * 8 + gid];
            mma_f16(acc[nc], a0, a1, a2, a3, b0, b1);
        }
    }

    if (mat == 0) {
        unsigned* oh = (unsigned*)g_xl2h;  // half2 view: index (r*CC+n)/2
#pragma unroll
        for (int nc = 0; nc < 5; nc++) {
            int n = nc * 8 + tig * 2;
            float b0v = __ldg(&bias[n]);
            float b1v = __ldg(&bias[n + 1]);
            if (r0 < NN) oh[(r0 * CC + n) >> 1] = f2h2(acc[nc][0] + b0v, acc[nc][1] + b1v);
            if (r1 < NN) oh[(r1 * CC + n) >> 1] = f2h2(acc[nc][2] + b0v, acc[nc][3] + b1v);
        }
    } else {
#pragma unroll
        for (int nc = 0; nc < 5; nc++) {
            int n = nc * 8 + tig * 2;
            float b0v = __ldg(&bias[n]);
            float b1v = __ldg(&bias[n + 1]);
            if (r0 < NN)
                *(float2*)&outp[r0 * CC + n] = make_float2(acc[nc][0] + b0v, acc[nc][1] + b1v);
            if (r1 < NN)
                *(float2*)&outp[r1 * CC + n] = make_float2(acc[nc][2] + b0v, acc[nc][3] + b1v);
        }
    }
}

// ---------------- layer2 attention + log_softmax: fp16 xl gathers --------------
__global__ void attn2_kernel(const float* __restrict__ att,
                             const float* __restrict__ bias2,
                             float* __restrict__ out) {
    int w = (blockIdx.x * blockDim.x + threadIdx.x) >> 5;
    int lane = threadIdx.x & 31;
    if (w >= NN) return;
    int grp = lane >> 4, sub = lane & 15;
    const bool act = (sub < 10);
    const unsigned gmask = 0xFFFFu << (grp * 16);

    float4 xr = make_float4(0.f, 0.f, 0.f, 0.f);
    float4 at = make_float4(0.f, 0.f, 0.f, 0.f);
    if (act) {
        xr = ((const float4*)g_xr2)[w * 10 + sub];
        at = ((const float4*)att)[sub];
    }

    int beg = g_roff[w], end = g_roff[w + 1];

    float mx = -1e30f, den = 0.f;
    float4 ac = make_float4(0.f, 0.f, 0.f, 0.f);

    int e = beg + grp;
    uint2 hv = make_uint2(0u, 0u);
    if (e < end && act) hv = g_xl2h[g_csrc[e] * 10 + sub];
    while (e < end) {
        int en = e + 2;
        uint2 hv2 = make_uint2(0u, 0u);
        if (en < end && act) hv2 = g_xl2h[g_csrc[en] * 10 + sub];
        float2 p0 = __half22float2(*(__half2*)&hv.x);
        float2 p1 = __half22float2(*(__half2*)&hv.y);
        float4 v = make_float4(p0.x, p0.y, p1.x, p1.y);
        float p = lrelu(v.x + xr.x) * at.x + lrelu(v.y + xr.y) * at.y
                + lrelu(v.z + xr.z) * at.z + lrelu(v.w + xr.w) * at.w;
        p += __shfl_xor_sync(gmask, p, 1);
        p += __shfl_xor_sync(gmask, p, 2);
        p += __shfl_xor_sync(gmask, p, 4);
        p += __shfl_xor_sync(gmask, p, 8);
        float nmx = fmaxf(mx, p);
        float sc = __expf(mx - nmx);
        float ww = __expf(p - nmx);
        den = fmaf(den, sc, ww);
        ac.x = fmaf(ac.x, sc, ww * v.x); ac.y = fmaf(ac.y, sc, ww * v.y);
        ac.z = fmaf(ac.z, sc, ww * v.z); ac.w = fmaf(ac.w, sc, ww * v.w);
        mx = nmx;
        e = en; hv = hv2;
    }

    {
        float omx = __shfl_xor_sync(0xffffffffu, mx, 16);
        float nmx = fmaxf(mx, omx);
        float sc = __expf(mx - nmx);
        den *= sc;
        ac.x *= sc; ac.y *= sc; ac.z *= sc; ac.w *= sc;
        den += __shfl_xor_sync(0xffffffffu, den, 16);
        ac.x += __shfl_xor_sync(0xffffffffu, ac.x, 16);
        ac.y += __shfl_xor_sync(0xffffffffu, ac.y, 16);
        ac.z += __shfl_xor_sync(0xffffffffu, ac.z, 16);
        ac.w += __shfl_xor_sync(0xffffffffu, ac.w, 16);
        mx = nmx;
    }

    float inv = 1.f / den;
    float4 o4 = make_float4(-1e30f, -1e30f, -1e30f, -1e30f);
    if (act) {
        float4 ln = ((const float4*)g_ln2)[w * 10 + sub];
        float4 b4 = ((const float4*)bias2)[sub];
        o4.x = fmaf(ac.x, inv, b4.x + ln.x);
        o4.y = fmaf(ac.y, inv, b4.y + ln.y);
        o4.z = fmaf(ac.z, inv, b4.z + ln.z);
        o4.w = fmaf(ac.w, inv, b4.w + ln.w);
    }
    float m2 = fmaxf(fmaxf(o4.x, o4.y), fmaxf(o4.z, o4.w));
#pragma unroll
    for (int o = 8; o > 0; o >>= 1) m2 = fmaxf(m2, __shfl_xor_sync(0xffffffffu, m2, o));
    float se = act ? (expf(o4.x - m2) + expf(o4.y - m2) + expf(o4.z - m2) + expf(o4.w - m2)) : 0.f;
#pragma unroll
    for (int o = 8; o > 0; o >>= 1) se += __shfl_xor_sync(0xffffffffu, se, o);
    float ls = m2 + logf(se);
    if (act && grp == 0) {
        float4 r;
        r.x = o4.x - ls; r.y = o4.y - ls; r.z = o4.z - ls; r.w = o4.w - ls;
        ((float4*)out)[w * 10 + sub] = r;
    }
}

// ---------------- launch (multi-stream: gemm1 overlaps CSR pipeline) ----------------
extern "C" void kernel_launch(void* const* d_in, const int* in_sizes, int n_in,
                              void* d_out, int out_size) {
    const float* x     = (const float*)d_in[0];
    const void*  ei    = d_in[1];
    const float* W1l   = (const float*)d_in[2];
    const float* b1l   = (const float*)d_in[3];
    const float* W1r   = (const float*)d_in[4];
    const float* b1r   = (const float*)d_in[5];
    const float* att1  = (const float*)d_in[6];
    const float* bias1 = (const float*)d_in[7];
    const float* l1W   = (const float*)d_in[8];
    const float* l1b   = (const float*)d_in[9];
    const float* W2l   = (const float*)d_in[10];
    const float* b2l   = (const float*)d_in[11];
    const float* W2r   = (const float*)d_in[12];
    const float* b2r   = (const float*)d_in[13];
    const float* att2  = (const float*)d_in[14];
    const float* bias2 = (const float*)d_in[15];
    const float* l2W   = (const float*)d_in[16];
    const float* l2b   = (const float*)d_in[17];
    float* out = (float*)d_out;
    int do_pass = (out_size >= NN * CC + 2 * EE) ? 1 : 0;

    static cudaStream_t s2 = nullptr;
    static cudaEvent_t e_fork = nullptr, e_join = nullptr;
    if (!s2) {
        cudaStreamCreateWithFlags(&s2, cudaStreamNonBlocking);
        cudaEventCreateWithFlags(&e_fork, cudaEventDisableTiming);
        cudaEventCreateWithFlags(&e_join, cudaEventDisableTiming);
    }

    cudaEventRecord(e_fork, 0);

    init_kernel<<<NB, 256>>>(ei);                                       // launch 0
    convert_count_kernel<<<(ET + 255) / 256, 256>>>(ei, out, do_pass);  // launch 1
    bsum_kernel<<<NB, 256>>>();                                         // launch 2

    cudaStreamWaitEvent(s2, e_fork, 0);
    gemm1_kernel<<<dim3((NN + 127) / 128, 3), 256, 0, s2>>>(            // launch 3: profiled
        x, W1l, b1l, W1r, b1r, l1W, l1b);
    cudaEventRecord(e_join, s2);

    bscan_kernel<<<1, 256>>>();
    offs_kernel<<<NB, 256>>>();
    scatter_kernel<<<(ET + 255) / 256, 256>>>();

    cudaStreamWaitEvent(0, e_join, 0);
    attn1_kernel<<<(NN * 32 + 255) / 256, 256>>>(att1, bias1);

    gemm2_kernel<<<dim3((NN + 127) / 128, 3), 256>>>(W2l, b2l, W2r, b2r, l2W, l2b);
    attn2_kernel<<<(NN * 32 + 255) / 256, 256>>>(att2, bias2, out);
}